// round 15
// baseline (speedup 1.0000x reference)
#include <cuda_runtime.h>

// AttnDecoder single decode step, fully fused persistent kernel.
// Phase 2 (logits matvec, 200MB stream) uses PER-WARP cp.async ring buffers:
// each warp owns a private 2-row (2x4KB) smem ring; while it runs its serial
// reduce/LSE tail, the next row's cp.async group is already streaming into
// smem -- DRAM never drains. No block-wide syncs (R10's killer), no register
// buffers (R7's killer).
// Output layout (float32, out_size = V + 2H):
//   [0, V)  log_probs   [V, V+H) h_new   [V+H, V+2H) c_new

#define H 1024
#define V 50000
#define NBLK 148
#define NTHR 768
#define NWARPS_BLK (NTHR / 32)          // 24
#define NWARP_TOT (NBLK * NWARPS_BLK)   // 3552
#define ROW_BYTES (H * 4)               // 4096

// Scratch (__device__ globals; no allocations allowed)
__device__ float g_gates[4 * H];
__device__ float g_pm[NBLK];
__device__ float g_ps[NBLK];
__device__ unsigned g_cnt[2];
__device__ unsigned g_gen[2];

// Sense-reversing grid barrier. All NBLK blocks are co-resident (1/SM).
__device__ __forceinline__ void gridbar(int id)
{
    __threadfence();          // publish this thread's prior writes
    __syncthreads();
    if (threadIdx.x == 0) {
        volatile unsigned* genp = &g_gen[id];
        const unsigned gen = *genp;              // read gen BEFORE arriving
        const unsigned t = atomicAdd(&g_cnt[id], 1u);
        if (t == NBLK - 1) {
            g_cnt[id] = 0;
            __threadfence();
            atomicAdd(&g_gen[id], 1u);           // release
        } else {
            while (*genp == gen) __nanosleep(64);
        }
    }
    __syncthreads();
    __threadfence();          // acquire side
}

// Warp sum via butterfly shuffles (redux.f32 not available on sm_103).
__device__ __forceinline__ float warp_sum(float v)
{
#pragma unroll
    for (int o = 16; o; o >>= 1) v += __shfl_xor_sync(0xFFFFFFFFu, v, o);
    return v;
}

// Streaming log-sum-exp merge of (m1,s1) <- (m1,s1)+(m2,s2)
__device__ __forceinline__ void lse_merge(float& m1, float& s1, float m2, float s2)
{
    const float M = fmaxf(m1, m2);
    s1 = s1 * expf(m1 - M) + s2 * expf(m2 - M);
    m1 = M;
}

// Issue one row (4KB) as 8x 16B cp.async.cg per lane, then commit the group.
// Lane l copies bytes [k*512 + l*16, +16) -- exactly the bytes lane l later
// consumes, so per-thread wait_group ordering suffices (no __syncwarp).
// pred==false still commits an (empty) group to keep accounting exact.
__device__ __forceinline__ void fill_row(unsigned sbase, const float* grow,
                                         int lane, bool pred)
{
    if (pred) {
        const char* g = (const char*)grow + lane * 16;
        const unsigned s = sbase + lane * 16;
#pragma unroll
        for (int k = 0; k < 8; k++) {
            asm volatile("cp.async.cg.shared.global [%0], [%1], 16;"
                         :: "r"(s + k * 512), "l"(g + k * 512));
        }
    }
    asm volatile("cp.async.commit_group;");
}

__global__ void __launch_bounds__(NTHR, 1) k_fused(
    const long long* __restrict__ tok_p,
    const float* __restrict__ emb,
    const float* __restrict__ h0,
    const float* __restrict__ c0,
    const float* __restrict__ W_ih,
    const float* __restrict__ W_hh,
    const float* __restrict__ b_ih,
    const float* __restrict__ b_hh,
    const float* __restrict__ out_W,
    const float* __restrict__ out_b,
    float* __restrict__ out)
{
    extern __shared__ __align__(16) float ring[];   // 24 warps x 2 x 1024 f
    __shared__ float se[H];       // embedded token
    __shared__ float sh[H];       // h0, later reused as h_new
    __shared__ float sm_m[NWARPS_BLK];
    __shared__ float sm_s[NWARPS_BLK];
    __shared__ float s_logZ;

    const int tid  = threadIdx.x;
    const int lane = tid & 31;
    const int wid  = tid >> 5;
    const int gwarp = blockIdx.x * NWARPS_BLK + wid;

    // ---- Phase 0: stage e and h0 in this block's smem --------------------
    {
        const long long tok = *tok_p;
        const float* erow = emb + tok * (long long)H;
        for (int t = tid; t < H; t += NTHR) {
            se[t] = erow[t];
            sh[t] = h0[t];
        }
    }
    __syncthreads();

    // ---- Phase 1: gate rows (4096 rows over 3552 warps; some do 2) ------
    for (int row = gwarp; row < 4 * H; row += NWARP_TOT) {
        const float4* wi = (const float4*)(W_ih + (long long)row * H);
        const float4* wh = (const float4*)(W_hh + (long long)row * H);
        const float4* e4 = (const float4*)se;
        const float4* h4 = (const float4*)sh;
        float s0 = 0.f, s1 = 0.f;
#pragma unroll
        for (int k = 0; k < H / 128; k++) {
            const int t = lane + k * 32;
            float4 a = wi[t], b = e4[t];
            s0 += a.x * b.x + a.y * b.y + a.z * b.z + a.w * b.w;
            float4 c = wh[t], d = h4[t];
            s1 += c.x * d.x + c.y * d.y + c.z * d.z + c.w * d.w;
        }
        float s = warp_sum(s0 + s1);
        if (lane == 0) g_gates[row] = s + b_ih[row] + b_hh[row];
    }

    gridbar(0);   // all gate pre-activations visible

    // ---- Phase 1b: LSTM elementwise; every block builds h_new in its smem
    for (int j = tid; j < H; j += NTHR) {
        const float gi = g_gates[j];
        const float gf = g_gates[H + j];
        const float gg = g_gates[2 * H + j];
        const float go = g_gates[3 * H + j];
        const float i_ = 1.f / (1.f + expf(-gi));
        const float f_ = 1.f / (1.f + expf(-gf));
        const float o_ = 1.f / (1.f + expf(-go));
        const float g_ = tanhf(gg);
        const float c_new = f_ * c0[j] + i_ * g_;
        const float h_new = o_ * tanhf(c_new);
        sh[j] = h_new;                       // reuse sh as h_new
        if (blockIdx.x == 0) {
            out[V + j]     = h_new;
            out[V + H + j] = c_new;
        }
    }
    __syncthreads();

    // ---- Phase 2: logits matvec with a per-warp 2-row cp.async ring -----
    float m_w = -1e30f, s_w = 0.f;
    {
        const unsigned sb0 = (unsigned)__cvta_generic_to_shared(
                                 ring + (wid * 2) * H);
        const unsigned sb1 = sb0 + ROW_BYTES;
        const float4* h4 = (const float4*)sh;

        // prologue: rows t and t+1 in flight (both < V: gwarp+3552 < 7104)
        fill_row(sb0, out_W + (long long)gwarp * H, lane, true);
        fill_row(sb1, out_W + (long long)(gwarp + NWARP_TOT) * H, lane, true);

        int b = 0;
        for (int row = gwarp; row < V; row += NWARP_TOT, b ^= 1) {
            // wait for the older group (this row's buffer)
            asm volatile("cp.async.wait_group 1;");

            // consume buf[b]: 4 independent accumulator chains
            const float4* wb = (const float4*)(ring + (wid * 2 + b) * H);
            float a0 = 0.f, a1 = 0.f, a2 = 0.f, a3 = 0.f;
#pragma unroll
            for (int k = 0; k < 8; k += 4) {
                const int t0 = lane + k * 32,       t1 = lane + (k + 1) * 32;
                const int t2 = lane + (k + 2) * 32, t3 = lane + (k + 3) * 32;
                float4 v, hh;
                v = wb[t0]; hh = h4[t0];
                a0 += v.x * hh.x + v.y * hh.y + v.z * hh.z + v.w * hh.w;
                v = wb[t1]; hh = h4[t1];
                a1 += v.x * hh.x + v.y * hh.y + v.z * hh.z + v.w * hh.w;
                v = wb[t2]; hh = h4[t2];
                a2 += v.x * hh.x + v.y * hh.y + v.z * hh.z + v.w * hh.w;
                v = wb[t3]; hh = h4[t3];
                a3 += v.x * hh.x + v.y * hh.y + v.z * hh.z + v.w * hh.w;
            }

            // refill this buffer with row+2*stride while we do the tail
            const int nr = row + 2 * NWARP_TOT;
            fill_row(b ? sb1 : sb0, out_W + (long long)nr * H, lane, nr < V);

            // serial tail -- next row's data is already streaming
            float s = warp_sum((a0 + a1) + (a2 + a3));
            const float x = s + out_b[row];      // uniform, broadcast
            if (lane == 0) out[row] = x;
            if (x > m_w) { s_w = s_w * expf(m_w - x) + 1.f; m_w = x; }
            else         { s_w += expf(x - m_w); }
        }
        asm volatile("cp.async.wait_group 0;");   // drain (empty tails)
    }
    if (lane == 0) { sm_m[wid] = m_w; sm_s[wid] = s_w; }
    __syncthreads();
    if (wid == 0) {
        float m = (lane < NWARPS_BLK) ? sm_m[lane] : -1e30f;
        float s = (lane < NWARPS_BLK) ? sm_s[lane] : 0.f;
#pragma unroll
        for (int o = 16; o; o >>= 1) {
            const float m2 = __shfl_xor_sync(0xFFFFFFFFu, m, o);
            const float s2 = __shfl_xor_sync(0xFFFFFFFFu, s, o);
            lse_merge(m, s, m2, s2);
        }
        if (lane == 0) { g_pm[blockIdx.x] = m; g_ps[blockIdx.x] = s; }
    }

    gridbar(1);   // all logits + partials visible

    // ---- Phase 3: combine 148 partials (warp 0, fixed order), subtract --
    if (wid == 0) {
        float m = -1e30f, s = 0.f;
        for (int b = lane; b < NBLK; b += 32)
            lse_merge(m, s, g_pm[b], g_ps[b]);
#pragma unroll
        for (int o = 16; o; o >>= 1) {
            const float m2 = __shfl_xor_sync(0xFFFFFFFFu, m, o);
            const float s2 = __shfl_xor_sync(0xFFFFFFFFu, s, o);
            lse_merge(m, s, m2, s2);
        }
        if (lane == 0) s_logZ = m + logf(s);
    }
    __syncthreads();
    const float logZ = s_logZ;
    for (int i = blockIdx.x * NTHR + tid; i < V; i += NBLK * NTHR)
        out[i] -= logZ;
}

extern "C" void kernel_launch(void* const* d_in, const int* in_sizes, int n_in,
                              void* d_out, int out_size)
{
    (void)in_sizes; (void)n_in; (void)out_size;
    const long long* tok  = (const long long*)d_in[0];
    const float* h0   = (const float*)d_in[1];
    const float* c0   = (const float*)d_in[2];
    // d_in[3] encoder_outputs, d_in[5..8] attn/comb params: dead code, skipped
    const float* emb  = (const float*)d_in[4];
    const float* W_ih = (const float*)d_in[9];
    const float* W_hh = (const float*)d_in[10];
    const float* b_ih = (const float*)d_in[11];
    const float* b_hh = (const float*)d_in[12];
    const float* outW = (const float*)d_in[13];
    const float* outb = (const float*)d_in[14];
    float* out = (float*)d_out;

    const int ring_bytes = NWARPS_BLK * 2 * ROW_BYTES;   // 196608
    cudaFuncSetAttribute(k_fused, cudaFuncAttributeMaxDynamicSharedMemorySize,
                         ring_bytes);
    k_fused<<<NBLK, NTHR, ring_bytes>>>(tok, emb, h0, c0, W_ih, W_hh,
                                        b_ih, b_hh, outW, outb, out);
}

// round 16
// speedup vs baseline: 1.1992x; 1.1992x over previous
#include <cuda_runtime.h>

// AttnDecoder single decode step, fully fused persistent kernel.
// R2 structure (proven best over 11 variants) + latency hoists:
//  - out_b[row] / b_ih[row] / b_hh[row] issued BEFORE the weight burst so
//    their cold-DRAM latency hides under the 8-LDG wait instead of adding a
//    ~577-cycle dependent stall to every row's serial tail.
//  - __expf in streaming LSE (single MUFU vs software expf sequence).
// Output layout (float32, out_size = V + 2H):
//   [0, V)  log_probs   [V, V+H) h_new   [V+H, V+2H) c_new

#define H 1024
#define V 50000
#define NBLK 148
#define NTHR 1024
#define NWARPS_BLK (NTHR / 32)          // 32
#define NWARP_TOT (NBLK * NWARPS_BLK)   // 4736

// Scratch (__device__ globals; no allocations allowed)
__device__ float g_gates[4 * H];
__device__ float g_pm[NBLK];
__device__ float g_ps[NBLK];
__device__ unsigned g_cnt[2];
__device__ unsigned g_gen[2];

// Sense-reversing grid barrier. All NBLK blocks are co-resident (1/SM).
__device__ __forceinline__ void gridbar(int id)
{
    __threadfence();          // publish this thread's prior writes
    __syncthreads();
    if (threadIdx.x == 0) {
        volatile unsigned* genp = &g_gen[id];
        const unsigned gen = *genp;              // read gen BEFORE arriving
        const unsigned t = atomicAdd(&g_cnt[id], 1u);
        if (t == NBLK - 1) {
            g_cnt[id] = 0;
            __threadfence();
            atomicAdd(&g_gen[id], 1u);           // release
        } else {
            while (*genp == gen) __nanosleep(64);
        }
    }
    __syncthreads();
    __threadfence();          // acquire side
}

// Warp sum via butterfly shuffles (redux.f32 not available on sm_103).
__device__ __forceinline__ float warp_sum(float v)
{
#pragma unroll
    for (int o = 16; o; o >>= 1) v += __shfl_xor_sync(0xFFFFFFFFu, v, o);
    return v;
}

// Streaming log-sum-exp merge of (m1,s1) <- (m1,s1)+(m2,s2). Fast exp:
// inputs are <= 0, result in [0,1]; __expf precision is ample for 1e-3 tol.
__device__ __forceinline__ void lse_merge(float& m1, float& s1, float m2, float s2)
{
    const float M = fmaxf(m1, m2);
    s1 = s1 * __expf(m1 - M) + s2 * __expf(m2 - M);
    m1 = M;
}

__global__ void __launch_bounds__(NTHR, 1) k_fused(
    const long long* __restrict__ tok_p,
    const float* __restrict__ emb,
    const float* __restrict__ h0,
    const float* __restrict__ c0,
    const float* __restrict__ W_ih,
    const float* __restrict__ W_hh,
    const float* __restrict__ b_ih,
    const float* __restrict__ b_hh,
    const float* __restrict__ out_W,
    const float* __restrict__ out_b,
    float* __restrict__ out)
{
    __shared__ float se[H];       // embedded token
    __shared__ float sh[H];       // h0, later reused as h_new
    __shared__ float sm_m[NWARPS_BLK];
    __shared__ float sm_s[NWARPS_BLK];
    __shared__ float s_logZ;

    const int tid  = threadIdx.x;
    const int lane = tid & 31;
    const int wid  = tid >> 5;
    const int gwarp = blockIdx.x * NWARPS_BLK + wid;

    // ---- Phase 0: stage e and h0 in this block's smem --------------------
    {
        const long long tok = *tok_p;
        const float* erow = emb + tok * (long long)H;
        for (int t = tid; t < H; t += NTHR) {
            se[t] = erow[t];
            sh[t] = h0[t];
        }
    }
    __syncthreads();

    // ---- Phase 1: gate rows. One warp per row of the 4H x H matvec pair.
    // Bias loads issued FIRST so they complete under the weight-load wait.
    if (gwarp < 4 * H) {
        const int row = gwarp;
        const float bias = b_ih[row] + b_hh[row];   // hoisted cold loads
        const float4* wi = (const float4*)(W_ih + (long long)row * H);
        const float4* wh = (const float4*)(W_hh + (long long)row * H);
        const float4* e4 = (const float4*)se;
        const float4* h4 = (const float4*)sh;
        float s = 0.f;
#pragma unroll
        for (int k = 0; k < H / 128; k++) {
            const int t = lane + k * 32;
            float4 a = wi[t], b = e4[t];
            s += a.x * b.x + a.y * b.y + a.z * b.z + a.w * b.w;
            float4 c = wh[t], d = h4[t];
            s += c.x * d.x + c.y * d.y + c.z * d.z + c.w * d.w;
        }
        s = warp_sum(s);
        if (lane == 0) g_gates[row] = s + bias;
    }

    gridbar(0);   // all gate pre-activations visible

    // ---- Phase 1b: LSTM elementwise; every block builds h_new in its smem
    for (int j = tid; j < H; j += NTHR) {
        const float gi = g_gates[j];
        const float gf = g_gates[H + j];
        const float gg = g_gates[2 * H + j];
        const float go = g_gates[3 * H + j];
        const float i_ = 1.f / (1.f + expf(-gi));
        const float f_ = 1.f / (1.f + expf(-gf));
        const float o_ = 1.f / (1.f + expf(-go));
        const float g_ = tanhf(gg);
        const float c_new = f_ * c0[j] + i_ * g_;
        const float h_new = o_ * tanhf(c_new);
        sh[j] = h_new;                       // reuse sh as h_new
        if (blockIdx.x == 0) {
            out[V + j]     = h_new;
            out[V + H + j] = c_new;
        }
    }
    __syncthreads();

    // ---- Phase 2: logits matvec, one row per warp per iteration (R2).
    // out_b[row] issued BEFORE the 8-LDG weight burst: its cold-DRAM latency
    // hides under the burst wait instead of stalling the serial tail.
    float m_w = -1e30f, s_w = 0.f;
    {
        const float4* h4 = (const float4*)sh;
        for (int row = gwarp; row < V; row += NWARP_TOT) {
            const float bias = out_b[row];          // hoisted cold load
            const float4* w = (const float4*)(out_W + (long long)row * H);
            float s = 0.f;
#pragma unroll
            for (int k = 0; k < 8; k++) {
                const int t = lane + k * 32;
                const float4 a = w[t], b = h4[t];
                s += a.x * b.x + a.y * b.y + a.z * b.z + a.w * b.w;
            }
            s = warp_sum(s);
            const float x = s + bias;
            if (lane == 0) out[row] = x;
            // streaming lse (identical in all lanes, fast exp)
            if (x > m_w) { s_w = s_w * __expf(m_w - x) + 1.f; m_w = x; }
            else         { s_w += __expf(x - m_w); }
        }
    }
    if (lane == 0) { sm_m[wid] = m_w; sm_s[wid] = s_w; }
    __syncthreads();
    if (wid == 0) {
        float m = sm_m[lane], s = sm_s[lane];
#pragma unroll
        for (int o = 16; o; o >>= 1) {
            const float m2 = __shfl_xor_sync(0xFFFFFFFFu, m, o);
            const float s2 = __shfl_xor_sync(0xFFFFFFFFu, s, o);
            lse_merge(m, s, m2, s2);
        }
        if (lane == 0) { g_pm[blockIdx.x] = m; g_ps[blockIdx.x] = s; }
    }

    gridbar(1);   // all logits + partials visible

    // ---- Phase 3: combine 148 partials (warp 0, fixed order), subtract --
    if (wid == 0) {
        float m = -1e30f, s = 0.f;
        for (int b = lane; b < NBLK; b += 32)
            lse_merge(m, s, g_pm[b], g_ps[b]);
#pragma unroll
        for (int o = 16; o; o >>= 1) {
            const float m2 = __shfl_xor_sync(0xFFFFFFFFu, m, o);
            const float s2 = __shfl_xor_sync(0xFFFFFFFFu, s, o);
            lse_merge(m, s, m2, s2);
        }
        if (lane == 0) s_logZ = m + logf(s);
    }
    __syncthreads();
    const float logZ = s_logZ;
    for (int i = blockIdx.x * NTHR + tid; i < V; i += NBLK * NTHR)
        out[i] -= logZ;
}

extern "C" void kernel_launch(void* const* d_in, const int* in_sizes, int n_in,
                              void* d_out, int out_size)
{
    (void)in_sizes; (void)n_in; (void)out_size;
    const long long* tok  = (const long long*)d_in[0];
    const float* h0   = (const float*)d_in[1];
    const float* c0   = (const float*)d_in[2];
    // d_in[3] encoder_outputs, d_in[5..8] attn/comb params: dead code, skipped
    const float* emb  = (const float*)d_in[4];
    const float* W_ih = (const float*)d_in[9];
    const float* W_hh = (const float*)d_in[10];
    const float* b_ih = (const float*)d_in[11];
    const float* b_hh = (const float*)d_in[12];
    const float* outW = (const float*)d_in[13];
    const float* outb = (const float*)d_in[14];
    float* out = (float*)d_out;

    k_fused<<<NBLK, NTHR>>>(tok, emb, h0, c0, W_ih, W_hh, b_ih, b_hh,
                            outW, outb, out);
}

// round 17
// speedup vs baseline: 1.2034x; 1.0035x over previous
#include <cuda_runtime.h>

// AttnDecoder single decode step, fully fused persistent kernel.
// R2 structure VERBATIM (best over 12 variants) + ONE additive change:
// at kernel entry each warp issues a register-free cp.async prefetch of its
// FIRST logits row (out_W[gwarp]) into smem. The copy streams during the
// phase-1 gates / barrier / LSTM window (DRAM-idle for out_W), and phase 2's
// iteration 0 consumes it from smem -- removing one of ~11 DRAM row-waits
// per warp from the phase-2 critical path.
// Output layout (float32, out_size = V + 2H):
//   [0, V)  log_probs   [V, V+H) h_new   [V+H, V+2H) c_new

#define H 1024
#define V 50000
#define NBLK 148
#define NTHR 1024
#define NWARPS_BLK (NTHR / 32)          // 32
#define NWARP_TOT (NBLK * NWARPS_BLK)   // 4736

// Scratch (__device__ globals; no allocations allowed)
__device__ float g_gates[4 * H];
__device__ float g_pm[NBLK];
__device__ float g_ps[NBLK];
__device__ unsigned g_cnt[2];
__device__ unsigned g_gen[2];

// Sense-reversing grid barrier. All NBLK blocks are co-resident (1/SM).
__device__ __forceinline__ void gridbar(int id)
{
    __threadfence();          // publish this thread's prior writes
    __syncthreads();
    if (threadIdx.x == 0) {
        volatile unsigned* genp = &g_gen[id];
        const unsigned gen = *genp;              // read gen BEFORE arriving
        const unsigned t = atomicAdd(&g_cnt[id], 1u);
        if (t == NBLK - 1) {
            g_cnt[id] = 0;
            __threadfence();
            atomicAdd(&g_gen[id], 1u);           // release
        } else {
            while (*genp == gen) __nanosleep(64);
        }
    }
    __syncthreads();
    __threadfence();          // acquire side
}

// Warp sum via butterfly shuffles (redux.f32 not available on sm_103).
__device__ __forceinline__ float warp_sum(float v)
{
#pragma unroll
    for (int o = 16; o; o >>= 1) v += __shfl_xor_sync(0xFFFFFFFFu, v, o);
    return v;
}

// Streaming log-sum-exp merge of (m1,s1) <- (m1,s1)+(m2,s2)
__device__ __forceinline__ void lse_merge(float& m1, float& s1, float m2, float s2)
{
    const float M = fmaxf(m1, m2);
    s1 = s1 * expf(m1 - M) + s2 * expf(m2 - M);
    m1 = M;
}

__global__ void __launch_bounds__(NTHR, 1) k_fused(
    const long long* __restrict__ tok_p,
    const float* __restrict__ emb,
    const float* __restrict__ h0,
    const float* __restrict__ c0,
    const float* __restrict__ W_ih,
    const float* __restrict__ W_hh,
    const float* __restrict__ b_ih,
    const float* __restrict__ b_hh,
    const float* __restrict__ out_W,
    const float* __restrict__ out_b,
    float* __restrict__ out)
{
    extern __shared__ __align__(16) float pre[];   // 32 warps x 1024 floats
    __shared__ float se[H];       // embedded token
    __shared__ float sh[H];       // h0, later reused as h_new
    __shared__ float sm_m[NWARPS_BLK];
    __shared__ float sm_s[NWARPS_BLK];
    __shared__ float s_logZ;

    const int tid  = threadIdx.x;
    const int lane = tid & 31;
    const int wid  = tid >> 5;
    const int gwarp = blockIdx.x * NWARPS_BLK + wid;

    // ---- Prefetch: this warp's FIRST logits row -> smem, fire-and-forget.
    // Lane l copies bytes [k*512 + l*16, +16) of out_W row gwarp -- exactly
    // the bytes lane l consumes in phase 2's iteration 0, so per-thread
    // cp.async ordering suffices (no extra sync).
    {
        const char* g = (const char*)(out_W + (long long)gwarp * H) + lane * 16;
        const unsigned s = (unsigned)__cvta_generic_to_shared(pre + wid * H)
                           + lane * 16;
#pragma unroll
        for (int k = 0; k < 8; k++) {
            asm volatile("cp.async.cg.shared.global [%0], [%1], 16;"
                         :: "r"(s + k * 512), "l"(g + k * 512));
        }
        asm volatile("cp.async.commit_group;");
    }

    // ---- Phase 0: stage e and h0 in this block's smem --------------------
    {
        const long long tok = *tok_p;
        const float* erow = emb + tok * (long long)H;
        for (int t = tid; t < H; t += NTHR) {
            se[t] = erow[t];
            sh[t] = h0[t];
        }
    }
    __syncthreads();

    // ---- Phase 1: gate rows. One warp per row of the 4H x H matvec pair --
    if (gwarp < 4 * H) {
        const int row = gwarp;
        const float4* wi = (const float4*)(W_ih + (long long)row * H);
        const float4* wh = (const float4*)(W_hh + (long long)row * H);
        const float4* e4 = (const float4*)se;
        const float4* h4 = (const float4*)sh;
        float s = 0.f;
#pragma unroll
        for (int k = 0; k < H / 128; k++) {
            const int t = lane + k * 32;
            float4 a = wi[t], b = e4[t];
            s += a.x * b.x + a.y * b.y + a.z * b.z + a.w * b.w;
            float4 c = wh[t], d = h4[t];
            s += c.x * d.x + c.y * d.y + c.z * d.z + c.w * d.w;
        }
        s = warp_sum(s);
        if (lane == 0) g_gates[row] = s + b_ih[row] + b_hh[row];
    }

    gridbar(0);   // all gate pre-activations visible

    // ---- Phase 1b: LSTM elementwise; every block builds h_new in its smem
    for (int j = tid; j < H; j += NTHR) {
        const float gi = g_gates[j];
        const float gf = g_gates[H + j];
        const float gg = g_gates[2 * H + j];
        const float go = g_gates[3 * H + j];
        const float i_ = 1.f / (1.f + expf(-gi));
        const float f_ = 1.f / (1.f + expf(-gf));
        const float o_ = 1.f / (1.f + expf(-go));
        const float g_ = tanhf(gg);
        const float c_new = f_ * c0[j] + i_ * g_;
        const float h_new = o_ * tanhf(c_new);
        sh[j] = h_new;                       // reuse sh as h_new
        if (blockIdx.x == 0) {
            out[V + j]     = h_new;
            out[V + H + j] = c_new;
        }
    }
    __syncthreads();

    // ---- Phase 2: logits matvec, one row per warp per iteration (R2).
    // Iteration 0 consumes the prefetched smem row; the rest hit global.
    float m_w = -1e30f, s_w = 0.f;
    {
        const float4* h4 = (const float4*)sh;

        // iteration 0: row gwarp from smem (always < V)
        {
            asm volatile("cp.async.wait_group 0;");
            const float4* wb = (const float4*)(pre + wid * H);
            float s = 0.f;
#pragma unroll
            for (int k = 0; k < 8; k++) {
                const int t = lane + k * 32;
                const float4 a = wb[t], b = h4[t];
                s += a.x * b.x + a.y * b.y + a.z * b.z + a.w * b.w;
            }
            s = warp_sum(s);
            const float x = s + out_b[gwarp];
            if (lane == 0) out[gwarp] = x;
            if (x > m_w) { s_w = s_w * expf(m_w - x) + 1.f; m_w = x; }
            else         { s_w += expf(x - m_w); }
        }

        // iterations 1..: untouched R2 loop
        for (int row = gwarp + NWARP_TOT; row < V; row += NWARP_TOT) {
            const float4* w = (const float4*)(out_W + (long long)row * H);
            float s = 0.f;
#pragma unroll
            for (int k = 0; k < 8; k++) {
                const int t = lane + k * 32;
                const float4 a = w[t], b = h4[t];
                s += a.x * b.x + a.y * b.y + a.z * b.z + a.w * b.w;
            }
            s = warp_sum(s);
            const float x = s + out_b[row];      // uniform, broadcast
            if (lane == 0) out[row] = x;
            // streaming lse (identical in all lanes)
            if (x > m_w) { s_w = s_w * expf(m_w - x) + 1.f; m_w = x; }
            else         { s_w += expf(x - m_w); }
        }
    }
    if (lane == 0) { sm_m[wid] = m_w; sm_s[wid] = s_w; }
    __syncthreads();
    if (wid == 0) {
        float m = sm_m[lane], s = sm_s[lane];
#pragma unroll
        for (int o = 16; o; o >>= 1) {
            const float m2 = __shfl_xor_sync(0xFFFFFFFFu, m, o);
            const float s2 = __shfl_xor_sync(0xFFFFFFFFu, s, o);
            lse_merge(m, s, m2, s2);
        }
        if (lane == 0) { g_pm[blockIdx.x] = m; g_ps[blockIdx.x] = s; }
    }

    gridbar(1);   // all logits + partials visible

    // ---- Phase 3: combine 148 partials (warp 0, fixed order), subtract --
    if (wid == 0) {
        float m = -1e30f, s = 0.f;
        for (int b = lane; b < NBLK; b += 32)
            lse_merge(m, s, g_pm[b], g_ps[b]);
#pragma unroll
        for (int o = 16; o; o >>= 1) {
            const float m2 = __shfl_xor_sync(0xFFFFFFFFu, m, o);
            const float s2 = __shfl_xor_sync(0xFFFFFFFFu, s, o);
            lse_merge(m, s, m2, s2);
        }
        if (lane == 0) s_logZ = m + logf(s);
    }
    __syncthreads();
    const float logZ = s_logZ;
    for (int i = blockIdx.x * NTHR + tid; i < V; i += NBLK * NTHR)
        out[i] -= logZ;
}

extern "C" void kernel_launch(void* const* d_in, const int* in_sizes, int n_in,
                              void* d_out, int out_size)
{
    (void)in_sizes; (void)n_in; (void)out_size;
    const long long* tok  = (const long long*)d_in[0];
    const float* h0   = (const float*)d_in[1];
    const float* c0   = (const float*)d_in[2];
    // d_in[3] encoder_outputs, d_in[5..8] attn/comb params: dead code, skipped
    const float* emb  = (const float*)d_in[4];
    const float* W_ih = (const float*)d_in[9];
    const float* W_hh = (const float*)d_in[10];
    const float* b_ih = (const float*)d_in[11];
    const float* b_hh = (const float*)d_in[12];
    const float* outW = (const float*)d_in[13];
    const float* outb = (const float*)d_in[14];
    float* out = (float*)d_out;

    const int pre_bytes = NWARPS_BLK * H * 4;    // 131072
    cudaFuncSetAttribute(k_fused, cudaFuncAttributeMaxDynamicSharedMemorySize,
                         pre_bytes);
    k_fused<<<NBLK, NTHR, pre_bytes>>>(tok, emb, h0, c0, W_ih, W_hh,
                                       b_ih, b_hh, outW, outb, out);
}